// round 10
// baseline (speedup 1.0000x reference)
#include <cuda_runtime.h>

#define NN 32
#define CC 64
#define TT 400
#define VV 27
#define SS 2
#define OO 64
#define LEAKK 0.1f
#define EPSS 1e-5f

#define TCH 25            // t-chunks for kernel A (16 t each, 8 pairs)

typedef unsigned long long ull;

__device__ __forceinline__ ull fma2(ull a, ull b, ull c) {
    ull d;
    asm("fma.rn.f32x2 %0, %1, %2, %3;" : "=l"(d) : "l"(a), "l"(b), "l"(c));
    return d;
}
__device__ __forceinline__ ull pk(float lo, float hi) {
    ull r;
    asm("mov.b64 %0, {%1, %2};" : "=l"(r) : "f"(lo), "f"(hi));
    return r;
}
__device__ __forceinline__ void upk(ull v, float& lo, float& hi) {
    asm("mov.b64 {%0, %1}, %2;" : "=f"(lo), "=f"(hi) : "l"(v));
}

// Scratch (static device globals — allocation-free)
__device__ float g_att_part[NN*TCH*SS*VV*VV];
__device__ float g_att[NN*SS*VV*VV];
__device__ float g_y2[(size_t)NN*TT*1792];      // [n][t][c*28+v], padded

// ---------------------------------------------------------------------------
// Kernel A: y = x + pe ; qk = W_in*y + b_in ; partial att accum over 16 t
// grid (25, NN), 512 threads. Packed over t-pairs; LDS.128 weight quads.
// ---------------------------------------------------------------------------
__global__ void __launch_bounds__(512,2) k_att_part(const float* __restrict__ x,
                                                    const float* __restrict__ pe,
                                                    const float* __restrict__ W_in,
                                                    const float* __restrict__ b_in) {
    extern __shared__ ull smU[];
    ull* sW2  = smU;            // 4096  (dup W_in, [c][o])
    ull* sy2  = sW2 + 4096;     // 1792  ([c][v] t-pair)
    ull* sqk2 = sy2 + 1792;     // 1792  ([o][v] t-pair)
    float* sb = (float*)(sqk2 + 1792);  // 64

    int n = blockIdx.y, chunk = blockIdx.x;
    int tid = threadIdx.x, og = tid >> 5, vv = tid & 31;

    for (int i = tid; i < 4096; i += 512) {
        int o = i & 63, c = i >> 6;
        float w = W_in[o*64 + c];
        sW2[i] = pk(w, w);
    }
    if (tid < 64) sb[tid] = b_in[tid];

    // att tiles: 2 s * 14 u2 * 14 v2 = 392 tiles of 2x2 (u,v); one per thread
    ull accA[4] = {0,0,0,0};
    int tileA = tid;                 // valid < 392
    int sA = tileA / 196; int rA = tileA - sA*196;
    int uA = (rA/14)*2, vA = (rA%14)*2;

    __syncthreads();

    for (int it = 0; it < 8; ++it) {
        int t0 = chunk*16 + it*2;
        for (int i = tid; i < 3456; i += 512) {
            int c = i / 54, r = i - c*54, tt = r / 27, v = r - tt*27;
            float val = x[(((size_t)n*64 + c)*400 + t0 + tt)*27 + v]
                      + pe[((size_t)c*400 + t0 + tt)*27 + v];
            ((float*)sy2)[2*(c*28 + v) + tt] = val;
        }
        __syncthreads();

        // projection: qk[o][vv] packed pair; 4 outputs per thread
        if (vv < 27) {
            ull acc[4];
            #pragma unroll
            for (int io = 0; io < 4; ++io) { float b = sb[og*4+io]; acc[io] = pk(b, b); }
            #pragma unroll 4
            for (int c = 0; c < 64; ++c) {
                ull yp = sy2[c*28 + vv];
                const ulonglong2* wrow = reinterpret_cast<const ulonglong2*>(sW2 + c*64 + og*4);
                ulonglong2 wA = wrow[0], wB = wrow[1];
                acc[0] = fma2(wA.x, yp, acc[0]);
                acc[1] = fma2(wA.y, yp, acc[1]);
                acc[2] = fma2(wB.x, yp, acc[2]);
                acc[3] = fma2(wB.y, yp, acc[3]);
            }
            #pragma unroll
            for (int io = 0; io < 4; ++io) sqk2[(og*4+io)*28 + vv] = acc[io];
        } else if (vv == 27) {
            // zero pad column so u+1 / v+1 loads are safe
            #pragma unroll
            for (int io = 0; io < 4; ++io) sqk2[(og*4+io)*28 + 27] = 0ULL;
        }
        __syncthreads();

        // q.k per 2x2 (u,v) tile; LDS.128 on (u,u+1) and (v,v+1) pairs
        if (tileA < 392) {
            const ull* q  = sqk2 + (sA*16)*28;
            const ull* kk = sqk2 + (32 + sA*16)*28;
            #pragma unroll 4
            for (int c = 0; c < 16; ++c) {
                ulonglong2 qp = *reinterpret_cast<const ulonglong2*>(q  + c*28 + uA);
                ulonglong2 kp = *reinterpret_cast<const ulonglong2*>(kk + c*28 + vA);
                accA[0] = fma2(qp.x, kp.x, accA[0]); accA[1] = fma2(qp.x, kp.y, accA[1]);
                accA[2] = fma2(qp.y, kp.x, accA[2]); accA[3] = fma2(qp.y, kp.y, accA[3]);
            }
        }
        __syncthreads();
    }

    // horizontal-reduce pairs and store partials
    if (tileA < 392) {
        float* base = g_att_part + (((size_t)n*TCH + chunk)*SS + sA)*729;
        float a0,b0; upk(accA[0],a0,b0); base[uA*27+vA] = a0+b0;
        float a1,b1; upk(accA[1],a1,b1);
        float a2,b2; upk(accA[2],a2,b2);
        float a3,b3; upk(accA[3],a3,b3);
        if (vA+1 < 27)              base[uA*27+vA+1]     = a1+b1;
        if (uA+1 < 27)              base[(uA+1)*27+vA]   = a2+b2;
        if (uA+1 < 27 && vA+1 < 27) base[(uA+1)*27+vA+1] = a3+b3;
    }
}

// ---------------------------------------------------------------------------
// Kernel B: reduce chunks + tanh/alpha/att0
// ---------------------------------------------------------------------------
__global__ void __launch_bounds__(256) k_att_final(const float* __restrict__ alphas,
                                                   const float* __restrict__ att0) {
    int idx = blockIdx.x*256 + threadIdx.x;
    if (idx >= NN*SS*729) return;
    int n = idx / (SS*729);
    int r = idx - n*(SS*729);
    int s = r / 729;
    int uv = r - s*729;
    float sum = 0.f;
    #pragma unroll
    for (int ch = 0; ch < TCH; ++ch)
        sum += g_att_part[(((size_t)n*TCH + ch)*SS + s)*729 + uv];
    g_att[idx] = tanhf(sum * (1.0f/6400.f)) * alphas[s] + att0[s*729 + uv];
}

// ---------------------------------------------------------------------------
// Kernel C: xa = x@att ; h = lrelu(x + bn(W_out xa)) ; y2 = lrelu(x + bn(W_ff h))
// grid (200, NN), 512 threads, 2 t per block.
// W stages packed over reduction-index pairs (j-pairs): acts LDS.64,
// weights [jp][o] so 4 o = 2 LDS.128; horizontal add at the end.
// ---------------------------------------------------------------------------
__global__ void __launch_bounds__(512,2) k_main(const float* __restrict__ x,
        const float* __restrict__ W_out, const float* __restrict__ b_out,
        const float* __restrict__ g_out, const float* __restrict__ be_out,
        const float* __restrict__ m_out, const float* __restrict__ v_out,
        const float* __restrict__ W_ff,  const float* __restrict__ b_ff,
        const float* __restrict__ g_ff,  const float* __restrict__ be_ff,
        const float* __restrict__ m_ff,  const float* __restrict__ v_ff) {
    extern __shared__ ull smU[];
    ull* sWoJP = smU;                     // 4096  [jp=64][o=64] = pk{W[o][2jp],W[o][2jp+1]}
    ull* sWfJP = sWoJP + 4096;            // 2048  [jp=32][o=64]
    ull* sx2   = sWfJP + 2048;            // 1792  ([c][u] t-pair {t0,t1})
    ull* sxaJP = sx2 + 1792;              // 3584  [jp=64][tt=2][v=28] = {xa[2jp],xa[2jp+1]}
    float* satt = (float*)(sxaJP + 3584); // 1458
    float* sscale_o = satt + 1458;
    float* sshift_o = sscale_o + 64;
    float* sscale_f = sshift_o + 64;
    float* sshift_f = sscale_f + 64;

    int n = blockIdx.y, tb = blockIdx.x;
    int tid = threadIdx.x, og = tid >> 5, vv = tid & 31;
    int t0 = tb*2;

    for (int idx = tid; idx < 4096; idx += 512) {
        int o = idx & 63, jp = idx >> 6;
        float2 w = *reinterpret_cast<const float2*>(W_out + o*128 + 2*jp);
        sWoJP[idx] = pk(w.x, w.y);
    }
    for (int idx = tid; idx < 2048; idx += 512) {
        int o = idx & 63, jp = idx >> 6;
        float2 w = *reinterpret_cast<const float2*>(W_ff + o*64 + 2*jp);
        sWfJP[idx] = pk(w.x, w.y);
    }
    for (int i = tid; i < 1458; i += 512) satt[i] = g_att[(size_t)n*1458 + i];
    if (tid < 64) {
        float sc = g_out[tid]*rsqrtf(v_out[tid]+EPSS);
        sscale_o[tid] = sc;
        sshift_o[tid] = be_out[tid] + sc*(b_out[tid]-m_out[tid]);
        float sf = g_ff[tid]*rsqrtf(v_ff[tid]+EPSS);
        sscale_f[tid] = sf;
        sshift_f[tid] = be_ff[tid] + sf*(b_ff[tid]-m_ff[tid]);
    }
    // stage x packed over the t-pair: sx2[c*28+u] = {x[t0], x[t0+1]}
    for (int i = tid; i < 3456; i += 512) {
        int c = i / 54, r = i - c*54, tt = r / 27, u = r - tt*27;
        ((float*)sx2)[2*(c*28+u) + tt] = x[(((size_t)n*64 + c)*400 + t0 + tt)*27 + u];
    }
    __syncthreads();

    // xa stage: t-packed; x loads warp-uniform, att per-lane.
    // Store into j-pair-interleaved layout for the W_out stage.
    if (vv < 27) {
        int s = og >> 3, c0 = (og & 7)*8;
        ull a[8] = {};
        #pragma unroll 3
        for (int u = 0; u < 27; ++u) {
            float av = satt[s*729 + u*27 + vv];
            ull av2 = pk(av, av);
            #pragma unroll
            for (int ci = 0; ci < 8; ++ci)
                a[ci] = fma2(sx2[(c0+ci)*28 + u], av2, a[ci]);
        }
        #pragma unroll
        for (int ci = 0; ci < 8; ++ci) {
            int j = s*64 + c0 + ci, jp = j >> 1, hf = j & 1;
            float f0, f1; upk(a[ci], f0, f1);
            ((float*)sxaJP)[(((jp*2+0)*28 + vv) << 1) + hf] = f0;
            ((float*)sxaJP)[(((jp*2+1)*28 + vv) << 1) + hf] = f1;
        }
    }
    __syncthreads();

    // W_out stage: j-pair packed; acc[io][tt] = {even-j sum, odd-j sum}
    float hv[4][2];
    if (vv < 27) {
        ull acc[4][2] = {};
        #pragma unroll 4
        for (int jp = 0; jp < 64; ++jp) {
            ull a0 = sxaJP[(jp*2)*28 + vv], a1 = sxaJP[(jp*2+1)*28 + vv];
            const ulonglong2* wr = reinterpret_cast<const ulonglong2*>(sWoJP + jp*64 + og*4);
            ulonglong2 wA = wr[0], wB = wr[1];
            acc[0][0] = fma2(wA.x, a0, acc[0][0]); acc[0][1] = fma2(wA.x, a1, acc[0][1]);
            acc[1][0] = fma2(wA.y, a0, acc[1][0]); acc[1][1] = fma2(wA.y, a1, acc[1][1]);
            acc[2][0] = fma2(wB.x, a0, acc[2][0]); acc[2][1] = fma2(wB.x, a1, acc[2][1]);
            acc[3][0] = fma2(wB.y, a0, acc[3][0]); acc[3][1] = fma2(wB.y, a1, acc[3][1]);
        }
        #pragma unroll
        for (int io = 0; io < 4; ++io) {
            int o = og*4 + io;
            float sc = sscale_o[o], sh = sshift_o[o];
            #pragma unroll
            for (int tt = 0; tt < 2; ++tt) {
                float e, od; upk(acc[io][tt], e, od);
                float f = e + od;
                float xr = ((float*)sx2)[2*(o*28+vv) + tt];
                float val = xr + f*sc + sh;
                hv[io][tt] = fmaxf(val, LEAKK*val);
            }
        }
    }
    __syncthreads();          // all sxaJP reads done
    if (vv < 27) {
        #pragma unroll
        for (int io = 0; io < 4; ++io) {
            int o = og*4 + io, jp = o >> 1, hf = o & 1;
            #pragma unroll
            for (int tt = 0; tt < 2; ++tt)
                ((float*)sxaJP)[(((jp*2+tt)*28 + vv) << 1) + hf] = hv[io][tt];
        }
    }
    __syncthreads();

    // W_ff stage -> y2 (global)
    if (vv < 27) {
        ull acc[4][2] = {};
        #pragma unroll 4
        for (int jp = 0; jp < 32; ++jp) {
            ull a0 = sxaJP[(jp*2)*28 + vv], a1 = sxaJP[(jp*2+1)*28 + vv];
            const ulonglong2* wr = reinterpret_cast<const ulonglong2*>(sWfJP + jp*64 + og*4);
            ulonglong2 wA = wr[0], wB = wr[1];
            acc[0][0] = fma2(wA.x, a0, acc[0][0]); acc[0][1] = fma2(wA.x, a1, acc[0][1]);
            acc[1][0] = fma2(wA.y, a0, acc[1][0]); acc[1][1] = fma2(wA.y, a1, acc[1][1]);
            acc[2][0] = fma2(wB.x, a0, acc[2][0]); acc[2][1] = fma2(wB.x, a1, acc[2][1]);
            acc[3][0] = fma2(wB.y, a0, acc[3][0]); acc[3][1] = fma2(wB.y, a1, acc[3][1]);
        }
        #pragma unroll
        for (int io = 0; io < 4; ++io) {
            int o = og*4 + io;
            float sc = sscale_f[o], sh = sshift_f[o];
            #pragma unroll
            for (int tt = 0; tt < 2; ++tt) {
                float e, od; upk(acc[io][tt], e, od);
                float f = e + od;
                float xr = ((float*)sx2)[2*(o*28+vv) + tt];
                float val = xr + f*sc + sh;
                val = fmaxf(val, LEAKK*val);
                g_y2[(size_t)(n*400 + t0 + tt)*1792 + o*28 + vv] = val;
            }
        }
    }
}

// ---------------------------------------------------------------------------
// Kernel D: z = lrelu(y2 + bn(conv_t(y2) + b_t)); 4 t per block.
// Packed over i-pairs: tile staged i-pair-interleaved, weights [r][o] pairs.
// grid (100, NN), 512 threads.
// ---------------------------------------------------------------------------
__global__ void __launch_bounds__(512,2) k_temporal(const float* __restrict__ W_t,
        const float* __restrict__ b_t, const float* __restrict__ g_t,
        const float* __restrict__ be_t, const float* __restrict__ m_t,
        const float* __restrict__ v_t, float* __restrict__ out) {
    extern __shared__ ull smU[];
    ull* sWtIP = smU;                       // 6144 [r=ip*3+tap (96)][o=64]
    ull* tile  = sWtIP + 6144;              // 6 slices x [ip=32][v=28] = 5376
    float* sscale = (float*)(tile + 5376);
    float* sshift = sscale + 64;

    int n = blockIdx.y, tb = blockIdx.x;
    int tid = threadIdx.x, og = tid >> 5, vv = tid & 31;
    int t0 = tb*4;

    // weights: pk{W_t[o][2ip][tap], W_t[o][2ip+1][tap]}
    for (int idx = tid; idx < 6144; idx += 512) {
        int o = idx & 63, r = idx >> 6;     // r = ip*3 + tap
        int ip = r / 3, tap = r - ip*3;
        const float* wb = W_t + o*192 + ip*6 + tap;
        sWtIP[idx] = pk(wb[0], wb[3]);
    }
    if (tid < 64) {
        float sc = g_t[tid]*rsqrtf(v_t[tid]+EPSS);
        sscale[tid] = sc;
        sshift[tid] = be_t[tid] + sc*(b_t[tid]-m_t[tid]);
    }
    #pragma unroll
    for (int k = 0; k < 6; ++k) {
        int t = t0 - 1 + k;
        float* dst = (float*)(tile + k*896);
        if (t >= 0 && t < 400) {
            const float* src = g_y2 + ((size_t)n*400 + t)*1792;
            for (int i = tid; i < 1792; i += 512) {
                int c = i / 28, v = i - c*28;
                dst[(((c>>1)*28 + v) << 1) + (c & 1)] = src[i];
            }
        } else {
            for (int i = tid; i < 1792; i += 512) dst[i] = 0.f;
        }
    }
    __syncthreads();

    if (vv < 27) {
        ull acc[4][4] = {};   // [io][tt], pairs over {even i, odd i}
        #pragma unroll 2
        for (int ip = 0; ip < 32; ++ip) {
            ull b[6];
            #pragma unroll
            for (int k = 0; k < 6; ++k) b[k] = tile[k*896 + ip*28 + vv];
            #pragma unroll
            for (int tap = 0; tap < 3; ++tap) {
                const ulonglong2* wr =
                    reinterpret_cast<const ulonglong2*>(sWtIP + (ip*3+tap)*64 + og*4);
                ulonglong2 wA = wr[0], wB = wr[1];
                #pragma unroll
                for (int tt = 0; tt < 4; ++tt) {
                    ull bk = b[tap + tt];
                    acc[0][tt] = fma2(wA.x, bk, acc[0][tt]);
                    acc[1][tt] = fma2(wA.y, bk, acc[1][tt]);
                    acc[2][tt] = fma2(wB.x, bk, acc[2][tt]);
                    acc[3][tt] = fma2(wB.y, bk, acc[3][tt]);
                }
            }
        }
        #pragma unroll
        for (int io = 0; io < 4; ++io) {
            int o = og*4 + io;
            float sc = sscale[o], sh = sshift[o];
            size_t ob = ((size_t)n*64 + o)*400;
            #pragma unroll
            for (int tt = 0; tt < 4; ++tt) {
                float e, od; upk(acc[io][tt], e, od);
                float f = e + od;
                float yr = ((float*)tile)[(((tt+1)*896 + (o>>1)*28 + vv) << 1) + (o & 1)];
                float val = yr + f*sc + sh;
                val = fmaxf(val, LEAKK*val);
                out[(ob + t0 + tt)*27 + vv] = val;
            }
        }
    }
}

// ---------------------------------------------------------------------------
extern "C" void kernel_launch(void* const* d_in, const int* in_sizes, int n_in,
                              void* d_out, int out_size) {
    const float* x      = (const float*)d_in[0];
    const float* pe     = (const float*)d_in[1];
    const float* W_in   = (const float*)d_in[2];
    const float* b_in   = (const float*)d_in[3];
    const float* alphas = (const float*)d_in[4];
    const float* att0   = (const float*)d_in[5];
    const float* W_out  = (const float*)d_in[6];
    const float* b_out  = (const float*)d_in[7];
    const float* g_out  = (const float*)d_in[8];
    const float* be_out = (const float*)d_in[9];
    const float* m_out  = (const float*)d_in[10];
    const float* v_out  = (const float*)d_in[11];
    const float* W_ff   = (const float*)d_in[12];
    const float* b_ff   = (const float*)d_in[13];
    const float* g_ff   = (const float*)d_in[14];
    const float* be_ff  = (const float*)d_in[15];
    const float* m_ff   = (const float*)d_in[16];
    const float* v_ff   = (const float*)d_in[17];
    const float* W_t    = (const float*)d_in[18];
    const float* b_t    = (const float*)d_in[19];
    const float* g_t    = (const float*)d_in[20];
    const float* be_t   = (const float*)d_in[21];
    const float* m_t    = (const float*)d_in[22];
    const float* v_t    = (const float*)d_in[23];
    float* out = (float*)d_out;

    const int smemA = 7680*8 + 64*4;                               // 61,696 B
    const int smemC = 11520*8 + (1458 + 256)*4;                    //  99,016 B
    const int smemD = 11520*8 + 128*4;                             //  92,672 B
    cudaFuncSetAttribute(k_att_part, cudaFuncAttributeMaxDynamicSharedMemorySize, smemA);
    cudaFuncSetAttribute(k_main,     cudaFuncAttributeMaxDynamicSharedMemorySize, smemC);
    cudaFuncSetAttribute(k_temporal, cudaFuncAttributeMaxDynamicSharedMemorySize, smemD);

    k_att_part<<<dim3(TCH, NN), 512, smemA>>>(x, pe, W_in, b_in);
    k_att_final<<<(NN*SS*729 + 255)/256, 256>>>(alphas, att0);
    k_main<<<dim3(TT/2, NN), 512, smemC>>>(x, W_out, b_out, g_out, be_out, m_out, v_out,
                                           W_ff, b_ff, g_ff, be_ff, m_ff, v_ff);
    k_temporal<<<dim3(TT/4, NN), 512, smemD>>>(W_t, b_t, g_t, be_t, m_t, v_t, out);
}

// round 11
// speedup vs baseline: 1.6109x; 1.6109x over previous
#include <cuda_runtime.h>

#define NN 32
#define CC 64
#define TT 400
#define VV 27
#define SS 2
#define OO 64
#define LEAKK 0.1f
#define EPSS 1e-5f

#define TCH 25            // t-chunks for kernel A (16 t each, 8 pairs)
#define TBD 6             // t per block, kernel D
#define NBD ((TT + TBD - 1)/TBD)   // 67

typedef unsigned long long ull;

__device__ __forceinline__ ull fma2(ull a, ull b, ull c) {
    ull d;
    asm("fma.rn.f32x2 %0, %1, %2, %3;" : "=l"(d) : "l"(a), "l"(b), "l"(c));
    return d;
}
__device__ __forceinline__ ull pk(float lo, float hi) {
    ull r;
    asm("mov.b64 %0, {%1, %2};" : "=l"(r) : "f"(lo), "f"(hi));
    return r;
}
__device__ __forceinline__ void upk(ull v, float& lo, float& hi) {
    asm("mov.b64 {%0, %1}, %2;" : "=f"(lo), "=f"(hi) : "l"(v));
}

// Scratch (static device globals — allocation-free)
__device__ float g_att_part[NN*TCH*SS*VV*VV];
__device__ float g_att[NN*SS*VV*VV];
__device__ float g_y2[(size_t)NN*TT*1792];      // [n][t][c*28+v], padded

// ---------------------------------------------------------------------------
// Kernel A: y = x + pe ; qk = W_in*y + b_in ; partial att accum over 16 t
// grid (25, NN), 512 threads (16 og x 4 outputs). Packed over t-pairs.
// ---------------------------------------------------------------------------
__global__ void __launch_bounds__(512,2) k_att_part(const float* __restrict__ x,
                                                    const float* __restrict__ pe,
                                                    const float* __restrict__ W_in,
                                                    const float* __restrict__ b_in) {
    extern __shared__ ull smU[];
    ull* sW2  = smU;            // 4096  (dup W_in, [c][o])
    ull* sy2  = sW2 + 4096;     // 1792  ([c][v] t-pair)
    ull* sqk2 = sy2 + 1792;     // 1792  ([o][v] t-pair)
    float* sb = (float*)(sqk2 + 1792);  // 64

    int n = blockIdx.y, chunk = blockIdx.x;
    int tid = threadIdx.x, og = tid >> 5, vv = tid & 31;

    for (int i = tid; i < 4096; i += 512) {
        int o = i & 63, c = i >> 6;
        float w = W_in[o*64 + c];
        sW2[i] = pk(w, w);
    }
    if (tid < 64) sb[tid] = b_in[tid];

    // att tiles: 2 s * 14 u2 * 14 v2 = 392 tiles of 2x2 (u,v); one per thread
    ull accA[4] = {0,0,0,0};
    int tileA = tid;                 // valid < 392
    int sA = tileA / 196; int rA = tileA - sA*196;
    int uA = (rA/14)*2, vA = (rA%14)*2;

    __syncthreads();

    for (int it = 0; it < 8; ++it) {
        int t0 = chunk*16 + it*2;
        for (int i = tid; i < 3456; i += 512) {
            int c = i / 54, r = i - c*54, tt = r / 27, v = r - tt*27;
            float val = x[(((size_t)n*64 + c)*400 + t0 + tt)*27 + v]
                      + pe[((size_t)c*400 + t0 + tt)*27 + v];
            ((float*)sy2)[2*(c*28 + v) + tt] = val;
        }
        __syncthreads();

        // projection: qk[o][vv] packed pair; 4 outputs per thread
        if (vv < 27) {
            ull acc[4];
            #pragma unroll
            for (int io = 0; io < 4; ++io) { float b = sb[og*4+io]; acc[io] = pk(b, b); }
            #pragma unroll 4
            for (int c = 0; c < 64; ++c) {
                ull yp = sy2[c*28 + vv];
                const ull* wrow = sW2 + c*64 + og*4;
                #pragma unroll
                for (int io = 0; io < 4; ++io)
                    acc[io] = fma2(wrow[io], yp, acc[io]);
            }
            #pragma unroll
            for (int io = 0; io < 4; ++io) sqk2[(og*4+io)*28 + vv] = acc[io];
        } else if (vv == 27) {
            // zero pad column so u+1 / v+1 loads are safe
            #pragma unroll
            for (int io = 0; io < 4; ++io) sqk2[(og*4+io)*28 + 27] = 0ULL;
        }
        __syncthreads();

        // q.k per 2x2 (u,v) tile, both t of the pair live in the two halves
        if (tileA < 392) {
            const ull* q  = sqk2 + (sA*16)*28;
            const ull* kk = sqk2 + (32 + sA*16)*28;
            #pragma unroll 4
            for (int c = 0; c < 16; ++c) {
                ull q0 = q[c*28+uA],  q1 = q[c*28+uA+1];
                ull k0 = kk[c*28+vA], k1 = kk[c*28+vA+1];
                accA[0] = fma2(q0,k0,accA[0]); accA[1] = fma2(q0,k1,accA[1]);
                accA[2] = fma2(q1,k0,accA[2]); accA[3] = fma2(q1,k1,accA[3]);
            }
        }
        __syncthreads();
    }

    // horizontal-reduce pairs and store partials
    if (tileA < 392) {
        float* base = g_att_part + (((size_t)n*TCH + chunk)*SS + sA)*729;
        float a0,b0; upk(accA[0],a0,b0); base[uA*27+vA] = a0+b0;
        float a1,b1; upk(accA[1],a1,b1);
        float a2,b2; upk(accA[2],a2,b2);
        float a3,b3; upk(accA[3],a3,b3);
        if (vA+1 < 27)              base[uA*27+vA+1]     = a1+b1;
        if (uA+1 < 27)              base[(uA+1)*27+vA]   = a2+b2;
        if (uA+1 < 27 && vA+1 < 27) base[(uA+1)*27+vA+1] = a3+b3;
    }
}

// ---------------------------------------------------------------------------
// Kernel B: reduce chunks + tanh/alpha/att0
// ---------------------------------------------------------------------------
__global__ void __launch_bounds__(256) k_att_final(const float* __restrict__ alphas,
                                                   const float* __restrict__ att0) {
    int idx = blockIdx.x*256 + threadIdx.x;
    if (idx >= NN*SS*729) return;
    int n = idx / (SS*729);
    int r = idx - n*(SS*729);
    int s = r / 729;
    int uv = r - s*729;
    float sum = 0.f;
    #pragma unroll
    for (int ch = 0; ch < TCH; ++ch)
        sum += g_att_part[(((size_t)n*TCH + ch)*SS + s)*729 + uv];
    g_att[idx] = tanhf(sum * (1.0f/6400.f)) * alphas[s] + att0[s*729 + uv];
}

// ---------------------------------------------------------------------------
// Kernel C: xa = x@att ; h = lrelu(x + bn(W_out xa)) ; y2 = lrelu(x + bn(W_ff h))
// grid (200, NN), 512 threads, 2 t per block. Weights packed over o-pairs
// (no duplication); xa stage packed over the t-pair; W stages o-packed.
// ---------------------------------------------------------------------------
__global__ void __launch_bounds__(512,2) k_main(const float* __restrict__ x,
        const float* __restrict__ W_out, const float* __restrict__ b_out,
        const float* __restrict__ g_out, const float* __restrict__ be_out,
        const float* __restrict__ m_out, const float* __restrict__ v_out,
        const float* __restrict__ W_ff,  const float* __restrict__ b_ff,
        const float* __restrict__ g_ff,  const float* __restrict__ be_ff,
        const float* __restrict__ m_ff,  const float* __restrict__ v_ff) {
    extern __shared__ ull smU[];
    ull* sWoP = smU;                      // 4096  ([j][op] pk{W[2op][j],W[2op+1][j]})
    ull* sWfP = sWoP + 4096;              // 2048
    ull* sx2  = sWfP + 2048;              // 1792  ([c][u] t-pair {t0,t1})
    float* sxaF = (float*)(sx2 + 1792);   // 7168  ([j][tt][v] scalars; reused for h)
    float* satt = sxaF + 7168;            // 1458
    float* sscale_o = satt + 1458;
    float* sshift_o = sscale_o + 64;
    float* sscale_f = sshift_o + 64;
    float* sshift_f = sscale_f + 64;

    int n = blockIdx.y, tb = blockIdx.x;
    int tid = threadIdx.x, og = tid >> 5, vv = tid & 31;
    int t0 = tb*2;

    for (int idx = tid; idx < 4096; idx += 512) {
        int op = idx & 31, j = idx >> 5;
        sWoP[idx] = pk(W_out[(2*op)*128 + j], W_out[(2*op+1)*128 + j]);
    }
    for (int idx = tid; idx < 2048; idx += 512) {
        int op = idx & 31, j = idx >> 5;
        sWfP[idx] = pk(W_ff[(2*op)*64 + j], W_ff[(2*op+1)*64 + j]);
    }
    for (int i = tid; i < 1458; i += 512) satt[i] = g_att[(size_t)n*1458 + i];
    if (tid < 64) {
        float sc = g_out[tid]*rsqrtf(v_out[tid]+EPSS);
        sscale_o[tid] = sc;
        sshift_o[tid] = be_out[tid] + sc*(b_out[tid]-m_out[tid]);
        float sf = g_ff[tid]*rsqrtf(v_ff[tid]+EPSS);
        sscale_f[tid] = sf;
        sshift_f[tid] = be_ff[tid] + sf*(b_ff[tid]-m_ff[tid]);
    }
    // stage x packed over the t-pair: sx2[c*28+u] = {x[t0], x[t0+1]}
    for (int i = tid; i < 3456; i += 512) {
        int c = i / 54, r = i - c*54, tt = r / 27, u = r - tt*27;
        ((float*)sx2)[2*(c*28+u) + tt] = x[(((size_t)n*64 + c)*400 + t0 + tt)*27 + u];
    }
    __syncthreads();

    // xa stage: t-packed; x loads warp-uniform, att per-lane
    if (vv < 27) {
        int s = og >> 3, c0 = (og & 7)*8;
        ull a[8] = {};
        #pragma unroll 3
        for (int u = 0; u < 27; ++u) {
            float av = satt[s*729 + u*27 + vv];
            ull av2 = pk(av, av);
            #pragma unroll
            for (int ci = 0; ci < 8; ++ci)
                a[ci] = fma2(sx2[(c0+ci)*28 + u], av2, a[ci]);
        }
        #pragma unroll
        for (int ci = 0; ci < 8; ++ci) {
            int j = s*64 + c0 + ci;
            float f0, f1; upk(a[ci], f0, f1);
            sxaF[(j*2)*28 + vv]   = f0;
            sxaF[(j*2+1)*28 + vv] = f1;
        }
    }
    __syncthreads();

    // W_out stage: o-packed accumulators acc[opl][tt]
    float hv[2][2][2];   // [opl][tt][even/odd o]
    {
        ull acc[2][2] = {};
        if (vv < 27) {
            #pragma unroll 4
            for (int j = 0; j < 128; ++j) {
                float a0 = sxaF[(j*2)*28 + vv], a1 = sxaF[(j*2+1)*28 + vv];
                ull b0 = pk(a0, a0), b1 = pk(a1, a1);
                ull w0 = sWoP[j*32 + og*2], w1 = sWoP[j*32 + og*2 + 1];
                acc[0][0] = fma2(w0, b0, acc[0][0]);
                acc[0][1] = fma2(w0, b1, acc[0][1]);
                acc[1][0] = fma2(w1, b0, acc[1][0]);
                acc[1][1] = fma2(w1, b1, acc[1][1]);
            }
            #pragma unroll
            for (int opl = 0; opl < 2; ++opl) {
                int o0 = og*4 + opl*2;
                float sc0 = sscale_o[o0],   sh0 = sshift_o[o0];
                float sc1 = sscale_o[o0+1], sh1 = sshift_o[o0+1];
                #pragma unroll
                for (int tt = 0; tt < 2; ++tt) {
                    float f0, f1; upk(acc[opl][tt], f0, f1);
                    float x0 = ((float*)sx2)[2*(o0*28+vv) + tt];
                    float x1 = ((float*)sx2)[2*((o0+1)*28+vv) + tt];
                    float v0 = x0 + f0*sc0 + sh0; v0 = fmaxf(v0, LEAKK*v0);
                    float v1 = x1 + f1*sc1 + sh1; v1 = fmaxf(v1, LEAKK*v1);
                    hv[opl][tt][0] = v0; hv[opl][tt][1] = v1;
                }
            }
        }
    }
    __syncthreads();          // all sxa reads done
    if (vv < 27) {
        #pragma unroll
        for (int opl = 0; opl < 2; ++opl) {
            int o0 = og*4 + opl*2;
            #pragma unroll
            for (int tt = 0; tt < 2; ++tt) {
                sxaF[(o0*2+tt)*28 + vv]     = hv[opl][tt][0];
                sxaF[((o0+1)*2+tt)*28 + vv] = hv[opl][tt][1];
            }
        }
    }
    __syncthreads();

    // W_ff stage -> y2 (global)
    if (vv < 27) {
        ull acc[2][2] = {};
        #pragma unroll 4
        for (int j = 0; j < 64; ++j) {
            float a0 = sxaF[(j*2)*28 + vv], a1 = sxaF[(j*2+1)*28 + vv];
            ull b0 = pk(a0, a0), b1 = pk(a1, a1);
            ull w0 = sWfP[j*32 + og*2], w1 = sWfP[j*32 + og*2 + 1];
            acc[0][0] = fma2(w0, b0, acc[0][0]);
            acc[0][1] = fma2(w0, b1, acc[0][1]);
            acc[1][0] = fma2(w1, b0, acc[1][0]);
            acc[1][1] = fma2(w1, b1, acc[1][1]);
        }
        #pragma unroll
        for (int opl = 0; opl < 2; ++opl) {
            int o0 = og*4 + opl*2;
            float sc0 = sscale_f[o0],   sh0 = sshift_f[o0];
            float sc1 = sscale_f[o0+1], sh1 = sshift_f[o0+1];
            #pragma unroll
            for (int tt = 0; tt < 2; ++tt) {
                float f0, f1; upk(acc[opl][tt], f0, f1);
                float x0 = ((float*)sx2)[2*(o0*28+vv) + tt];
                float x1 = ((float*)sx2)[2*((o0+1)*28+vv) + tt];
                float v0 = x0 + f0*sc0 + sh0; v0 = fmaxf(v0, LEAKK*v0);
                float v1 = x1 + f1*sc1 + sh1; v1 = fmaxf(v1, LEAKK*v1);
                size_t row = (size_t)(n*400 + t0 + tt)*1792;
                g_y2[row + o0*28 + vv]     = v0;
                g_y2[row + (o0+1)*28 + vv] = v1;
            }
        }
    }
}

// ---------------------------------------------------------------------------
// Kernel D: z = lrelu(y2 + bn(conv_t(y2) + b_t)); 6 t per block, o-packed.
// grid (67, NN), 512 threads (16 og x 2 opairs x 6 t). 8 smem slices.
// ---------------------------------------------------------------------------
__global__ void __launch_bounds__(512,2) k_temporal(const float* __restrict__ W_t,
        const float* __restrict__ b_t, const float* __restrict__ g_t,
        const float* __restrict__ be_t, const float* __restrict__ m_t,
        const float* __restrict__ v_t, float* __restrict__ out) {
    extern __shared__ ull smU[];
    ull* sWtP = smU;                        // 6144  ([(i*3+tap)][op] o-pairs)
    float* tile   = (float*)(sWtP + 6144);  // 8 * 1792
    float* sscale = tile + 8*1792;
    float* sshift = sscale + 64;

    int n = blockIdx.y, tb = blockIdx.x;
    int tid = threadIdx.x, og = tid >> 5, vv = tid & 31;
    int t0 = tb*TBD;

    for (int idx = tid; idx < 6144; idx += 512) {
        int op = idx & 31, r = idx >> 5;     // r = i*3+tap
        sWtP[idx] = pk(W_t[(2*op)*192 + r], W_t[(2*op+1)*192 + r]);
    }
    if (tid < 64) {
        float sc = g_t[tid]*rsqrtf(v_t[tid]+EPSS);
        sscale[tid] = sc;
        sshift[tid] = be_t[tid] + sc*(b_t[tid]-m_t[tid]);
    }
    #pragma unroll
    for (int k = 0; k < TBD+2; ++k) {
        int t = t0 - 1 + k;
        ull* dst = (ull*)(tile + k*1792);
        if (t >= 0 && t < 400) {
            const ull* src = (const ull*)(g_y2 + ((size_t)n*400 + t)*1792);
            for (int i = tid; i < 896; i += 512) dst[i] = src[i];
        } else {
            for (int i = tid; i < 896; i += 512) dst[i] = 0ULL;
        }
    }
    __syncthreads();

    if (vv < 27) {
        ull acc[2][TBD] = {};
        #pragma unroll 2
        for (int i = 0; i < 64; ++i) {
            ull bp[TBD+2];
            #pragma unroll
            for (int k = 0; k < TBD+2; ++k) {
                float a = tile[k*1792 + i*28 + vv];
                bp[k] = pk(a, a);
            }
            #pragma unroll
            for (int opl = 0; opl < 2; ++opl) {
                const ull* w = sWtP + (i*3)*32 + og*2 + opl;
                ull w0 = w[0], w1 = w[32], w2 = w[64];
                #pragma unroll
                for (int tt = 0; tt < TBD; ++tt) {
                    acc[opl][tt] = fma2(w0, bp[tt],   acc[opl][tt]);
                    acc[opl][tt] = fma2(w1, bp[tt+1], acc[opl][tt]);
                    acc[opl][tt] = fma2(w2, bp[tt+2], acc[opl][tt]);
                }
            }
        }
        #pragma unroll
        for (int opl = 0; opl < 2; ++opl) {
            int o0 = og*4 + opl*2;
            float sc0 = sscale[o0],   sh0 = sshift[o0];
            float sc1 = sscale[o0+1], sh1 = sshift[o0+1];
            size_t ob0 = ((size_t)n*64 + o0)*400;
            size_t ob1 = ((size_t)n*64 + o0+1)*400;
            #pragma unroll
            for (int tt = 0; tt < TBD; ++tt) {
                if (t0 + tt >= 400) break;
                float f0, f1; upk(acc[opl][tt], f0, f1);
                float y0 = tile[(tt+1)*1792 + o0*28 + vv];
                float y1 = tile[(tt+1)*1792 + (o0+1)*28 + vv];
                float v0 = y0 + f0*sc0 + sh0; v0 = fmaxf(v0, LEAKK*v0);
                float v1 = y1 + f1*sc1 + sh1; v1 = fmaxf(v1, LEAKK*v1);
                out[(ob0 + t0 + tt)*27 + vv] = v0;
                out[(ob1 + t0 + tt)*27 + vv] = v1;
            }
        }
    }
}

// ---------------------------------------------------------------------------
extern "C" void kernel_launch(void* const* d_in, const int* in_sizes, int n_in,
                              void* d_out, int out_size) {
    const float* x      = (const float*)d_in[0];
    const float* pe     = (const float*)d_in[1];
    const float* W_in   = (const float*)d_in[2];
    const float* b_in   = (const float*)d_in[3];
    const float* alphas = (const float*)d_in[4];
    const float* att0   = (const float*)d_in[5];
    const float* W_out  = (const float*)d_in[6];
    const float* b_out  = (const float*)d_in[7];
    const float* g_out  = (const float*)d_in[8];
    const float* be_out = (const float*)d_in[9];
    const float* m_out  = (const float*)d_in[10];
    const float* v_out  = (const float*)d_in[11];
    const float* W_ff   = (const float*)d_in[12];
    const float* b_ff   = (const float*)d_in[13];
    const float* g_ff   = (const float*)d_in[14];
    const float* be_ff  = (const float*)d_in[15];
    const float* m_ff   = (const float*)d_in[16];
    const float* v_ff   = (const float*)d_in[17];
    const float* W_t    = (const float*)d_in[18];
    const float* b_t    = (const float*)d_in[19];
    const float* g_t    = (const float*)d_in[20];
    const float* be_t   = (const float*)d_in[21];
    const float* m_t    = (const float*)d_in[22];
    const float* v_t    = (const float*)d_in[23];
    float* out = (float*)d_out;

    const int smemA = 7680*8 + 64*4;                               // 61,696 B
    const int smemC = 7936*8 + (7168 + 1458 + 256)*4;              //  99,016 B
    const int smemD = 6144*8 + (8*1792 + 128)*4;                   // 107,008 B
    cudaFuncSetAttribute(k_att_part, cudaFuncAttributeMaxDynamicSharedMemorySize, smemA);
    cudaFuncSetAttribute(k_main,     cudaFuncAttributeMaxDynamicSharedMemorySize, smemC);
    cudaFuncSetAttribute(k_temporal, cudaFuncAttributeMaxDynamicSharedMemorySize, smemD);

    k_att_part<<<dim3(TCH, NN), 512, smemA>>>(x, pe, W_in, b_in);
    k_att_final<<<(NN*SS*729 + 255)/256, 256>>>(alphas, att0);
    k_main<<<dim3(TT/2, NN), 512, smemC>>>(x, W_out, b_out, g_out, be_out, m_out, v_out,
                                           W_ff, b_ff, g_ff, be_ff, m_ff, v_ff);
    k_temporal<<<dim3(NBD, NN), 512, smemD>>>(W_t, b_t, g_t, be_t, m_t, v_t, out);
}